// round 14
// baseline (speedup 1.0000x reference)
#include <cuda_runtime.h>
#include <cstdint>

// B=256 batches of N=512 x 512 binary (0/1) float32 adjacency.
constexpr int B   = 256;
constexpr int N   = 512;
constexpr int W   = N / 32;    // 16 packed words per row
constexpr int F4  = N / 4;     // 128 float4 per row
constexpr int QB  = B / 4;     // 64 batches per pipeline quarter
constexpr int RPC1 = 32;       // rows per CTA, pack kernel
constexpr int GRID1 = QB * (N / RPC1);  // 1024 pack CTAs per quarter
constexpr int RPC2 = 64;       // rows per CTA, scale kernel
constexpr int GRID2 = QB * (N / RPC2);  // 512 scale CTAs per quarter

// Scratch (__device__ globals: allocation-free rule).
// Transposed slot layout: word t lives at slot (t&3)*4 + (t>>2), so the uint4
// at slot-index g = words {g, 4+g, 8+g, 12+g} (exactly what K2 consumes).
__device__ unsigned g_bits[(size_t)B * N * W];  // 8 MB (L2-resident)
__device__ float    g_dis [(size_t)B * N];      // 512 KB

// ---------------------------------------------------------------------------
// Pack: one warp per row, ballot packing (proven R10 body). 32 rows/CTA.
// Independent of all other kernels; fence + PDL trigger at end.
// ---------------------------------------------------------------------------
__global__ void __launch_bounds__(256)
pack_kernel(const float* __restrict__ adj, int base_batch) {
    const int bid   = blockIdx.x;
    const int batch = base_batch + (bid >> 4);
    const int r0    = (bid & 15) * RPC1;

    const int tid  = threadIdx.x;
    const int wid  = tid >> 5;
    const int lane = tid & 31;
    const int l16  = lane & 15;

    const float* base = adj + ((size_t)batch * N + r0 + wid * 4) * N;

    #pragma unroll
    for (int k = 0; k < 2; k++) {
        const float* p0 = base + (size_t)(2 * k)     * N;
        const float* p1 = base + (size_t)(2 * k + 1) * N;

        // Front-batch 2 rows = 32 independent coalesced LDG.32 (128B/wavefront).
        float a[W], b[W];
        #pragma unroll
        for (int t = 0; t < W; t++) {
            a[t] = __ldcs(&p0[t * 32 + lane]);
            b[t] = __ldcs(&p1[t * 32 + lane]);
        }

        #pragma unroll
        for (int r = 0; r < 2; r++) {
            const float* x = (r == 0) ? a : b;
            const int ig = r0 + wid * 4 + 2 * k + r;   // row index within batch

            // 16 independent ballots; lane l keeps word l (l<16).
            unsigned myw = 0;
            #pragma unroll
            for (int t = 0; t < W; t++) {
                unsigned bt = __ballot_sync(0xffffffffu, x[t] != 0.0f);
                if (l16 == t) myw = bt;
            }

            int cnt = __popc(myw);
            cnt += __shfl_xor_sync(0xffffffffu, cnt, 1);
            cnt += __shfl_xor_sync(0xffffffffu, cnt, 2);
            cnt += __shfl_xor_sync(0xffffffffu, cnt, 4);
            cnt += __shfl_xor_sync(0xffffffffu, cnt, 8);

            const int dw = ig >> 5, db = ig & 31;
            const unsigned diagw = __shfl_sync(0xffffffffu, myw, dw);
            const int diag = (diagw >> db) & 1;
            const int mask = (cnt != 0) ? 1 : 0;       // atom_mask
            const int deg  = cnt - diag + mask;        // degree_hat
            if (diag != mask && l16 == dw) myw ^= (1u << db);

            // Transposed-slot store: word l -> slot (l&3)*4 + (l>>2).
            if (lane < 16)
                g_bits[((size_t)batch * N + ig) * W + (lane & 3) * 4 + (lane >> 2)] = myw;
            if (lane == 0)
                g_dis[(size_t)batch * N + ig] = (deg > 0) ? rsqrtf((float)deg) : 0.0f;
        }
    }

    // Release for the dependent scale quarter: visibility, then trigger.
    __threadfence();
    cudaTriggerProgrammaticLaunchCompletion();
}

// ---------------------------------------------------------------------------
// Scale: out[i][j] = dis[i]*dis[j]*bit(i,j) (proven R8/R10 body, write-capped).
// Gate on own quarter's pack triggers, then trigger IMMEDIATELY so the next
// pack quarter launches and its read stream overlaps this write stream.
// ---------------------------------------------------------------------------
__global__ void __launch_bounds__(256)
scale_kernel(float* __restrict__ out, int base_batch) {
    const int bid   = blockIdx.x;
    const int batch = base_batch + (bid >> 3);
    const int r0    = (bid & 7) * RPC2;

    const int tid  = threadIdx.x;
    const int wid  = tid >> 5;
    const int lane = tid & 31;
    const int sub  = lane & 7;
    const int grp  = lane >> 3;

    const int lr = r0 + wid * 8;   // first of 8 rows for this warp (within batch)

    // Acquire own quarter's pack data, then immediately open the next gate.
    cudaGridDependencySynchronize();
    cudaTriggerProgrammaticLaunchCompletion();

    // Row-invariant column scales: dreg[c] = dis[c*128 + lane*4 .. +3].
    const float4* d4 = reinterpret_cast<const float4*>(g_dis + (size_t)batch * N);
    float4 dreg[4];
    #pragma unroll
    for (int c = 0; c < 4; c++) dreg[c] = __ldg(&d4[c * 32 + lane]);

    // Front-batch the 8 rows' packed words (one aligned uint4 per lane-group,
    // L2-resident) and the 8 row scales.
    const uint4* b4 = reinterpret_cast<const uint4*>(g_bits)
                    + ((size_t)batch * N + lr) * 4;
    uint4 wb[8];
    #pragma unroll
    for (int r = 0; r < 8; r++) wb[r] = __ldcg(&b4[(size_t)r * 4 + grp]);

    float di[8];
    #pragma unroll
    for (int r = 0; r < 8; r++) di[r] = __ldg(&g_dis[(size_t)batch * N + lr + r]);

    float4* o4 = reinterpret_cast<float4*>(out) + ((size_t)batch * N + lr) * F4;

    #pragma unroll
    for (int r = 0; r < 8; r++) {
        float4* q = o4 + (size_t)r * F4;
        const unsigned wc[4] = {wb[r].x, wb[r].y, wb[r].z, wb[r].w};  // word c*4+grp
        #pragma unroll
        for (int c = 0; c < 4; c++) {
            const unsigned nib = (wc[c] >> (sub * 4)) & 0xFu;
            const float4 d = dreg[c];
            float4 o;
            o.x = (nib & 1u) ? di[r] * d.x : 0.0f;
            o.y = (nib & 2u) ? di[r] * d.y : 0.0f;
            o.z = (nib & 4u) ? di[r] * d.z : 0.0f;
            o.w = (nib & 8u) ? di[r] * d.w : 0.0f;
            __stcs(&q[c * 32 + lane], o);  // coalesced STG.128 stream
        }
    }
}

// Helper: PSS launch (kernel launches once the previous kernel in the stream
// has triggered, not when it drains).
template <typename K, typename... Args>
static void launch_pss(K kernel, int grid, Args... args) {
    cudaLaunchConfig_t cfg = {};
    cfg.gridDim  = dim3(grid);
    cfg.blockDim = dim3(256);
    cudaLaunchAttribute attr[1];
    attr[0].id = cudaLaunchAttributeProgrammaticStreamSerialization;
    attr[0].val.programmaticStreamSerializationAllowed = 1;
    cfg.attrs = attr;
    cfg.numAttrs = 1;
    cudaLaunchKernelEx(&cfg, kernel, args...);
}

extern "C" void kernel_launch(void* const* d_in, const int* in_sizes, int n_in,
                              void* d_out, int out_size) {
    const float* adj = (const float*)d_in[0];
    float* out = (float*)d_out;
    (void)in_sizes; (void)n_in; (void)out_size;

    // Quarter-pipelined chain: P0, S0, P1, S1, P2, S2, P3, S3.
    // S_q gates on P_q (data), triggers immediately -> P_{q+1}'s reads overlap
    // S_q's writes. Packs have no entry gate (fully independent quarters).
    pack_kernel<<<GRID1, 256>>>(adj, 0 * QB);
    launch_pss(scale_kernel, GRID2, out, 0 * QB);
    #pragma unroll
    for (int q = 1; q < 4; q++) {
        launch_pss(pack_kernel,  GRID1, adj, q * QB);
        launch_pss(scale_kernel, GRID2, out, q * QB);
    }
}

// round 15
// speedup vs baseline: 1.0773x; 1.0773x over previous
#include <cuda_runtime.h>
#include <cstdint>

// B=256 batches of N=512 x 512 binary (0/1) float32 adjacency.
constexpr int B   = 256;
constexpr int N   = 512;
constexpr int W   = N / 32;    // 16 packed words per row
constexpr int F4  = N / 4;     // 128 float4 per row
constexpr int HB  = B / 2;     // 128 batches per half
constexpr int RPC1 = 32;       // rows per CTA, pack kernel
constexpr int GRID1H = HB * (N / RPC1);  // 2048 pack CTAs per half
constexpr int RPC2 = 64;       // rows per CTA, scale kernel
constexpr int GRID2H = HB * (N / RPC2);  // 1024 scale CTAs per half

// Scratch (__device__ globals: allocation-free rule).
// Transposed slot layout: word t lives at slot (t&3)*4 + (t>>2), so the uint4
// at slot-index g = words {g, 4+g, 8+g, 12+g} (exactly what K2 consumes).
__device__ unsigned g_bits[(size_t)B * N * W];  // 8 MB (L2-resident)
__device__ float    g_dis [(size_t)B * N];      // 512 KB

// ---------------------------------------------------------------------------
// Pack: one warp per row, ballot packing (proven R10 body). 32 rows/CTA;
// 2 rows front-batched (32 independent coalesced LDG.32).
// ---------------------------------------------------------------------------
__global__ void __launch_bounds__(256)
pack_kernel(const float* __restrict__ adj, int base_batch) {
    const int bid   = blockIdx.x;
    const int batch = base_batch + (bid >> 4);
    const int r0    = (bid & 15) * RPC1;

    const int tid  = threadIdx.x;
    const int wid  = tid >> 5;
    const int lane = tid & 31;
    const int l16  = lane & 15;

    const float* base = adj + ((size_t)batch * N + r0 + wid * 4) * N;

    #pragma unroll
    for (int k = 0; k < 2; k++) {
        const float* p0 = base + (size_t)(2 * k)     * N;
        const float* p1 = base + (size_t)(2 * k + 1) * N;

        // Front-batch 2 rows = 32 independent coalesced LDG.32 (128B/wavefront).
        float a[W], b[W];
        #pragma unroll
        for (int t = 0; t < W; t++) {
            a[t] = __ldcs(&p0[t * 32 + lane]);
            b[t] = __ldcs(&p1[t * 32 + lane]);
        }

        #pragma unroll
        for (int r = 0; r < 2; r++) {
            const float* x = (r == 0) ? a : b;
            const int ig = r0 + wid * 4 + 2 * k + r;   // row index within batch

            // 16 independent ballots; lane l keeps word l (l<16).
            unsigned myw = 0;
            #pragma unroll
            for (int t = 0; t < W; t++) {
                unsigned bt = __ballot_sync(0xffffffffu, x[t] != 0.0f);
                if (l16 == t) myw = bt;
            }

            // Degree: popc of own word, xor-reduce over the 16-lane group.
            int cnt = __popc(myw);
            cnt += __shfl_xor_sync(0xffffffffu, cnt, 1);
            cnt += __shfl_xor_sync(0xffffffffu, cnt, 2);
            cnt += __shfl_xor_sync(0xffffffffu, cnt, 4);
            cnt += __shfl_xor_sync(0xffffffffu, cnt, 8);

            const int dw = ig >> 5, db = ig & 31;
            const unsigned diagw = __shfl_sync(0xffffffffu, myw, dw);
            const int diag = (diagw >> db) & 1;
            const int mask = (cnt != 0) ? 1 : 0;       // atom_mask
            const int deg  = cnt - diag + mask;        // degree_hat
            if (diag != mask && l16 == dw) myw ^= (1u << db);

            // Transposed-slot store: word l -> slot (l&3)*4 + (l>>2).
            if (lane < 16)
                g_bits[((size_t)batch * N + ig) * W + (lane & 3) * 4 + (lane >> 2)] = myw;
            if (lane == 0)
                g_dis[(size_t)batch * N + ig] = (deg > 0) ? rsqrtf((float)deg) : 0.0f;
        }
    }
}

// ---------------------------------------------------------------------------
// Scale: out[i][j] = dis[i]*dis[j]*bit(i,j). Proven R8/R10 body (write cap).
// 8 warps x 8 rows = 64 rows/CTA; no smem, no barriers.
// ---------------------------------------------------------------------------
__global__ void __launch_bounds__(256)
scale_kernel(float* __restrict__ out, int base_batch) {
    const int bid   = blockIdx.x;
    const int batch = base_batch + (bid >> 3);
    const int r0    = (bid & 7) * RPC2;

    const int tid  = threadIdx.x;
    const int wid  = tid >> 5;
    const int lane = tid & 31;
    const int sub  = lane & 7;
    const int grp  = lane >> 3;

    const int lr = r0 + wid * 8;   // first of 8 rows for this warp (within batch)

    // Row-invariant column scales: dreg[c] = dis[c*128 + lane*4 .. +3].
    const float4* d4 = reinterpret_cast<const float4*>(g_dis + (size_t)batch * N);
    float4 dreg[4];
    #pragma unroll
    for (int c = 0; c < 4; c++) dreg[c] = __ldg(&d4[c * 32 + lane]);

    // Front-batch the 8 rows' packed words (one aligned uint4 per lane-group,
    // L2-resident) and the 8 row scales.
    const uint4* b4 = reinterpret_cast<const uint4*>(g_bits)
                    + ((size_t)batch * N + lr) * 4;
    uint4 wb[8];
    #pragma unroll
    for (int r = 0; r < 8; r++) wb[r] = __ldcg(&b4[(size_t)r * 4 + grp]);

    float di[8];
    #pragma unroll
    for (int r = 0; r < 8; r++) di[r] = __ldg(&g_dis[(size_t)batch * N + lr + r]);

    float4* o4 = reinterpret_cast<float4*>(out) + ((size_t)batch * N + lr) * F4;

    #pragma unroll
    for (int r = 0; r < 8; r++) {
        float4* q = o4 + (size_t)r * F4;
        const unsigned wc[4] = {wb[r].x, wb[r].y, wb[r].z, wb[r].w};  // word c*4+grp
        #pragma unroll
        for (int c = 0; c < 4; c++) {
            const unsigned nib = (wc[c] >> (sub * 4)) & 0xFu;
            const float4 d = dreg[c];
            float4 o;
            o.x = (nib & 1u) ? di[r] * d.x : 0.0f;
            o.y = (nib & 2u) ? di[r] * d.y : 0.0f;
            o.z = (nib & 4u) ? di[r] * d.z : 0.0f;
            o.w = (nib & 8u) ? di[r] * d.w : 0.0f;
            __stcs(&q[c * 32 + lane], o);  // coalesced STG.128 stream
        }
    }
}

extern "C" void kernel_launch(void* const* d_in, const int* in_sizes, int n_in,
                              void* d_out, int out_size) {
    const float* adj = (const float*)d_in[0];
    float* out = (float*)d_out;
    (void)in_sizes; (void)n_in; (void)out_size;

    // Graph-branch pipeline at half granularity:
    //   P0 -> { S0 (branch stream) || P1 (main stream) } -> S1
    // Middle phase mixes a 128MB read stream with a 128MB write stream.
    // Stream/event creation happens only on the few host invocations of
    // kernel_launch (graph replays never re-enter this function); objects are
    // intentionally not destroyed while capture is in progress.
    cudaStream_t s2;
    cudaStreamCreateWithFlags(&s2, cudaStreamNonBlocking);
    cudaEvent_t e1, e2;
    cudaEventCreateWithFlags(&e1, cudaEventDisableTiming);
    cudaEventCreateWithFlags(&e2, cudaEventDisableTiming);

    // P0: pack first half (read stream only).
    pack_kernel<<<GRID1H, 256>>>(adj, 0);
    cudaEventRecord(e1, 0);

    // Branch: S0 (writes, depends on P0) runs concurrently with P1 (reads).
    cudaStreamWaitEvent(s2, e1, 0);
    scale_kernel<<<GRID2H, 256, 0, s2>>>(out, 0);
    pack_kernel<<<GRID1H, 256>>>(adj, HB);

    // Join: S1 after P1 (program order) and S0 (event edge).
    cudaEventRecord(e2, s2);
    cudaStreamWaitEvent(0, e2, 0);
    scale_kernel<<<GRID2H, 256>>>(out, HB);
}

// round 16
// speedup vs baseline: 1.1402x; 1.0584x over previous
#include <cuda_runtime.h>
#include <cstdint>

// B=256 batches of N=512 x 512 binary (0/1) float32 adjacency.
constexpr int B   = 256;
constexpr int N   = 512;
constexpr int W   = N / 32;    // 16 packed words per row
constexpr int F4  = N / 4;     // 128 float4 per row
constexpr int RPC1 = 32;       // rows per CTA, pack kernel
constexpr int GRID1 = B * (N / RPC1);  // 4096
constexpr int RPC2 = 64;       // rows per CTA, scale kernel
constexpr int GRID2 = B * (N / RPC2);  // 2048

// Scratch (__device__ globals: allocation-free rule).
// Transposed slot layout: word t lives at slot (t&3)*4 + (t>>2), so the uint4
// at slot-index g = words {g, 4+g, 8+g, 12+g} (exactly what K2 consumes).
__device__ unsigned g_bits[(size_t)B * N * W];  // 8 MB (L2-resident)
__device__ float    g_dis [(size_t)B * N];      // 512 KB

// ---------------------------------------------------------------------------
// K1: one warp per row, ballot packing (proven R10 body). 8 warps x 4 rows =
// 32 rows/CTA; 2 rows front-batched (32 independent coalesced LDG.32).
// ---------------------------------------------------------------------------
__global__ void __launch_bounds__(256)
pack_kernel(const float* __restrict__ adj) {
    const int bid   = blockIdx.x;
    const int batch = bid >> 4;
    const int r0    = (bid & 15) * RPC1;

    const int tid  = threadIdx.x;
    const int wid  = tid >> 5;
    const int lane = tid & 31;
    const int l16  = lane & 15;

    const float* base = adj + ((size_t)batch * N + r0 + wid * 4) * N;

    #pragma unroll
    for (int k = 0; k < 2; k++) {
        const float* p0 = base + (size_t)(2 * k)     * N;
        const float* p1 = base + (size_t)(2 * k + 1) * N;

        // Front-batch 2 rows = 32 independent coalesced LDG.32 (128B/wavefront).
        float a[W], b[W];
        #pragma unroll
        for (int t = 0; t < W; t++) {
            a[t] = __ldcs(&p0[t * 32 + lane]);
            b[t] = __ldcs(&p1[t * 32 + lane]);
        }

        #pragma unroll
        for (int r = 0; r < 2; r++) {
            const float* x = (r == 0) ? a : b;
            const int ig = r0 + wid * 4 + 2 * k + r;   // row index within batch

            // 16 independent ballots; lane l keeps word l (l<16).
            unsigned myw = 0;
            #pragma unroll
            for (int t = 0; t < W; t++) {
                unsigned bt = __ballot_sync(0xffffffffu, x[t] != 0.0f);
                if (l16 == t) myw = bt;
            }

            // Degree: popc of own word, xor-reduce over the 16-lane group.
            int cnt = __popc(myw);
            cnt += __shfl_xor_sync(0xffffffffu, cnt, 1);
            cnt += __shfl_xor_sync(0xffffffffu, cnt, 2);
            cnt += __shfl_xor_sync(0xffffffffu, cnt, 4);
            cnt += __shfl_xor_sync(0xffffffffu, cnt, 8);

            const int dw = ig >> 5, db = ig & 31;
            const unsigned diagw = __shfl_sync(0xffffffffu, myw, dw);
            const int diag = (diagw >> db) & 1;
            const int mask = (cnt != 0) ? 1 : 0;       // atom_mask
            const int deg  = cnt - diag + mask;        // degree_hat
            if (diag != mask && l16 == dw) myw ^= (1u << db);

            // Transposed-slot store: word l -> slot (l&3)*4 + (l>>2).
            if (lane < 16)
                g_bits[((size_t)batch * N + ig) * W + (lane & 3) * 4 + (lane >> 2)] = myw;
            if (lane == 0)
                g_dis[(size_t)batch * N + ig] = (deg > 0) ? rsqrtf((float)deg) : 0.0f;
        }
    }
}

// ---------------------------------------------------------------------------
// K2: out[i][j] = dis[i]*dis[j]*bit(i,j). R10 body with ONE change: output
// stores are write-through (__stwt) so no dirty L2 residue survives the
// replay boundary to stall the next replay's pack reads.
// ---------------------------------------------------------------------------
__global__ void __launch_bounds__(256)
scale_kernel(float* __restrict__ out) {
    const int bid   = blockIdx.x;
    const int batch = bid >> 3;
    const int r0    = (bid & 7) * RPC2;

    const int tid  = threadIdx.x;
    const int wid  = tid >> 5;
    const int lane = tid & 31;
    const int sub  = lane & 7;
    const int grp  = lane >> 3;

    const int lr = r0 + wid * 8;   // first of 8 rows for this warp (within batch)

    // PDL: wait until pack_kernel's writes are visible, then proceed.
    cudaGridDependencySynchronize();

    // Row-invariant column scales: dreg[c] = dis[c*128 + lane*4 .. +3].
    const float4* d4 = reinterpret_cast<const float4*>(g_dis + (size_t)batch * N);
    float4 dreg[4];
    #pragma unroll
    for (int c = 0; c < 4; c++) dreg[c] = __ldg(&d4[c * 32 + lane]);

    // Front-batch the 8 rows' packed words (one aligned uint4 per lane-group,
    // L2-resident) and the 8 row scales.
    const uint4* b4 = reinterpret_cast<const uint4*>(g_bits)
                    + ((size_t)batch * N + lr) * 4;
    uint4 wb[8];
    #pragma unroll
    for (int r = 0; r < 8; r++) wb[r] = __ldcg(&b4[(size_t)r * 4 + grp]);

    float di[8];
    #pragma unroll
    for (int r = 0; r < 8; r++) di[r] = __ldg(&g_dis[(size_t)batch * N + lr + r]);

    float4* o4 = reinterpret_cast<float4*>(out) + ((size_t)batch * N + lr) * F4;

    #pragma unroll
    for (int r = 0; r < 8; r++) {
        float4* q = o4 + (size_t)r * F4;
        const unsigned wc[4] = {wb[r].x, wb[r].y, wb[r].z, wb[r].w};  // word c*4+grp
        #pragma unroll
        for (int c = 0; c < 4; c++) {
            const unsigned nib = (wc[c] >> (sub * 4)) & 0xFu;
            const float4 d = dreg[c];
            float4 o;
            o.x = (nib & 1u) ? di[r] * d.x : 0.0f;
            o.y = (nib & 2u) ? di[r] * d.y : 0.0f;
            o.z = (nib & 4u) ? di[r] * d.z : 0.0f;
            o.w = (nib & 8u) ? di[r] * d.w : 0.0f;
            __stwt(&q[c * 32 + lane], o);  // write-through STG.128: no L2 residue
        }
    }
}

extern "C" void kernel_launch(void* const* d_in, const int* in_sizes, int n_in,
                              void* d_out, int out_size) {
    const float* adj = (const float*)d_in[0];
    float* out = (float*)d_out;
    (void)in_sizes; (void)n_in; (void)out_size;

    pack_kernel<<<GRID1, 256>>>(adj);

    // PDL launch (R10 config, proven best): K2 CTAs spin up during K1's tail
    // wave; dependency enforced by cudaGridDependencySynchronize() in K2.
    cudaLaunchConfig_t cfg = {};
    cfg.gridDim  = dim3(GRID2);
    cfg.blockDim = dim3(256);
    cudaLaunchAttribute attr[1];
    attr[0].id = cudaLaunchAttributeProgrammaticStreamSerialization;
    attr[0].val.programmaticStreamSerializationAllowed = 1;
    cfg.attrs = attr;
    cfg.numAttrs = 1;
    cudaLaunchKernelEx(&cfg, scale_kernel, out);
}

// round 17
// speedup vs baseline: 1.1579x; 1.0155x over previous
#include <cuda_runtime.h>
#include <cstdint>

// B=256 batches of N=512 x 512 binary (0/1) float32 adjacency.
constexpr int B   = 256;
constexpr int N   = 512;
constexpr int W   = N / 32;    // 16 packed words per row
constexpr int F4  = N / 4;     // 128 float4 per row
constexpr int RPC1 = 64;       // rows per CTA, pack kernel (16 warps x 4 rows)
constexpr int GRID1 = B * (N / RPC1);  // 2048
constexpr int RPC2 = 128;      // rows per CTA, scale kernel (16 warps x 8 rows)
constexpr int GRID2 = B * (N / RPC2);  // 1024

// Scratch (__device__ globals: allocation-free rule).
// Transposed slot layout: word t lives at slot (t&3)*4 + (t>>2), so the uint4
// at slot-index g = words {g, 4+g, 8+g, 12+g} (exactly what K2 consumes).
__device__ unsigned g_bits[(size_t)B * N * W];  // 8 MB (L2-resident)
__device__ float    g_dis [(size_t)B * N];      // 512 KB

// ---------------------------------------------------------------------------
// K1: one warp per row, ballot packing (proven body). 16 warps x 4 rows =
// 64 rows/CTA; 2 rows front-batched (32 independent coalesced LDG.32).
// ---------------------------------------------------------------------------
__global__ void __launch_bounds__(512)
pack_kernel(const float* __restrict__ adj) {
    const int bid   = blockIdx.x;
    const int batch = bid >> 3;            // 8 CTAs per batch
    const int r0    = (bid & 7) * RPC1;

    const int tid  = threadIdx.x;
    const int wid  = tid >> 5;             // 0..15
    const int lane = tid & 31;
    const int l16  = lane & 15;

    const float* base = adj + ((size_t)batch * N + r0 + wid * 4) * N;

    #pragma unroll
    for (int k = 0; k < 2; k++) {
        const float* p0 = base + (size_t)(2 * k)     * N;
        const float* p1 = base + (size_t)(2 * k + 1) * N;

        // Front-batch 2 rows = 32 independent coalesced LDG.32 (128B/wavefront).
        float a[W], b[W];
        #pragma unroll
        for (int t = 0; t < W; t++) {
            a[t] = __ldcs(&p0[t * 32 + lane]);
            b[t] = __ldcs(&p1[t * 32 + lane]);
        }

        #pragma unroll
        for (int r = 0; r < 2; r++) {
            const float* x = (r == 0) ? a : b;
            const int ig = r0 + wid * 4 + 2 * k + r;   // row index within batch

            // 16 independent ballots; lane l keeps word l (l<16).
            unsigned myw = 0;
            #pragma unroll
            for (int t = 0; t < W; t++) {
                unsigned bt = __ballot_sync(0xffffffffu, x[t] != 0.0f);
                if (l16 == t) myw = bt;
            }

            // Degree: popc of own word, xor-reduce over the 16-lane group.
            int cnt = __popc(myw);
            cnt += __shfl_xor_sync(0xffffffffu, cnt, 1);
            cnt += __shfl_xor_sync(0xffffffffu, cnt, 2);
            cnt += __shfl_xor_sync(0xffffffffu, cnt, 4);
            cnt += __shfl_xor_sync(0xffffffffu, cnt, 8);

            const int dw = ig >> 5, db = ig & 31;
            const unsigned diagw = __shfl_sync(0xffffffffu, myw, dw);
            const int diag = (diagw >> db) & 1;
            const int mask = (cnt != 0) ? 1 : 0;       // atom_mask
            const int deg  = cnt - diag + mask;        // degree_hat
            if (diag != mask && l16 == dw) myw ^= (1u << db);

            // Transposed-slot store: word l -> slot (l&3)*4 + (l>>2).
            if (lane < 16)
                g_bits[((size_t)batch * N + ig) * W + (lane & 3) * 4 + (lane >> 2)] = myw;
            if (lane == 0)
                g_dis[(size_t)batch * N + ig] = (deg > 0) ? rsqrtf((float)deg) : 0.0f;
        }
    }
}

// ---------------------------------------------------------------------------
// K2: out[i][j] = dis[i]*dis[j]*bit(i,j). Proven body with __stwt output
// (no dirty-L2 replay residue). 16 warps x 8 rows = 128 rows/CTA. PDL entry.
// ---------------------------------------------------------------------------
__global__ void __launch_bounds__(512)
scale_kernel(float* __restrict__ out) {
    const int bid   = blockIdx.x;
    const int batch = bid >> 2;            // 4 CTAs per batch
    const int r0    = (bid & 3) * RPC2;

    const int tid  = threadIdx.x;
    const int wid  = tid >> 5;             // 0..15
    const int lane = tid & 31;
    const int sub  = lane & 7;
    const int grp  = lane >> 3;

    const int lr = r0 + wid * 8;   // first of 8 rows for this warp (within batch)

    // PDL: wait until pack_kernel's writes are visible, then proceed.
    cudaGridDependencySynchronize();

    // Row-invariant column scales: dreg[c] = dis[c*128 + lane*4 .. +3].
    const float4* d4 = reinterpret_cast<const float4*>(g_dis + (size_t)batch * N);
    float4 dreg[4];
    #pragma unroll
    for (int c = 0; c < 4; c++) dreg[c] = __ldg(&d4[c * 32 + lane]);

    // Front-batch the 8 rows' packed words (one aligned uint4 per lane-group,
    // L2-resident) and the 8 row scales.
    const uint4* b4 = reinterpret_cast<const uint4*>(g_bits)
                    + ((size_t)batch * N + lr) * 4;
    uint4 wb[8];
    #pragma unroll
    for (int r = 0; r < 8; r++) wb[r] = __ldcg(&b4[(size_t)r * 4 + grp]);

    float di[8];
    #pragma unroll
    for (int r = 0; r < 8; r++) di[r] = __ldg(&g_dis[(size_t)batch * N + lr + r]);

    float4* o4 = reinterpret_cast<float4*>(out) + ((size_t)batch * N + lr) * F4;

    #pragma unroll
    for (int r = 0; r < 8; r++) {
        float4* q = o4 + (size_t)r * F4;
        const unsigned wc[4] = {wb[r].x, wb[r].y, wb[r].z, wb[r].w};  // word c*4+grp
        #pragma unroll
        for (int c = 0; c < 4; c++) {
            const unsigned nib = (wc[c] >> (sub * 4)) & 0xFu;
            const float4 d = dreg[c];
            float4 o;
            o.x = (nib & 1u) ? di[r] * d.x : 0.0f;
            o.y = (nib & 2u) ? di[r] * d.y : 0.0f;
            o.z = (nib & 4u) ? di[r] * d.z : 0.0f;
            o.w = (nib & 8u) ? di[r] * d.w : 0.0f;
            __stwt(&q[c * 32 + lane], o);  // write-through STG.128: no L2 residue
        }
    }
}

extern "C" void kernel_launch(void* const* d_in, const int* in_sizes, int n_in,
                              void* d_out, int out_size) {
    const float* adj = (const float*)d_in[0];
    float* out = (float*)d_out;
    (void)in_sizes; (void)n_in; (void)out_size;

    pack_kernel<<<GRID1, 512>>>(adj);

    // PDL launch (proven best config): K2 CTAs spin up during K1's tail wave;
    // dependency enforced by cudaGridDependencySynchronize() in K2.
    cudaLaunchConfig_t cfg = {};
    cfg.gridDim  = dim3(GRID2);
    cfg.blockDim = dim3(512);
    cudaLaunchAttribute attr[1];
    attr[0].id = cudaLaunchAttributeProgrammaticStreamSerialization;
    attr[0].val.programmaticStreamSerializationAllowed = 1;
    cfg.attrs = attr;
    cfg.numAttrs = 1;
    cudaLaunchKernelEx(&cfg, scale_kernel, out);
}